// round 10
// baseline (speedup 1.0000x reference)
#include <cuda_runtime.h>
#include <cuda_bf16.h>
#include <math.h>
#include <stdint.h>

// Problem dims (fixed): B=4, T=8192, D=512, H=512
#define BB 4
#define TT 8192
#define DD 512
#define HH 512
#define NC 64
#define CL (TT / NC)
#define MROWS (BB * TT)      // 32768 flattened rows

// ---------------- scratch (allocation-free contract) ----------------
__device__ __align__(16) float2 g_cv[(size_t)BB * TT * HH];        // 128 MB
__device__ float2 g_agg[BB * NC * HH];
__device__ float  g_pref[BB * NC * HH];
__device__ __align__(16) __nv_bfloat16 g_xhi[(size_t)MROWS * DD];  // 32 MB
__device__ __align__(16) __nv_bfloat16 g_xlo[(size_t)MROWS * DD];  // 32 MB
__device__ __align__(16) __nv_bfloat16 g_bhi[(size_t)1024 * DD];   // packed: row R -> (R&1? Wh : Wz)[R>>1]
__device__ __align__(16) __nv_bfloat16 g_blo[(size_t)1024 * DD];

// ---------------- helpers ----------------
__device__ __forceinline__ uint32_t smem_u32(const void* p) {
    uint32_t a;
    asm("{ .reg .u64 t; cvta.to.shared.u64 t, %1; cvt.u32.u64 %0, t; }" : "=r"(a) : "l"(p));
    return a;
}
__device__ __forceinline__ void cpasync16(uint32_t dst, const void* src) {
    asm volatile("cp.async.cg.shared.global [%0], [%1], 16;" :: "r"(dst), "l"(src));
}
__device__ __forceinline__ void ldsm_x4(uint32_t* r, uint32_t addr) {
    asm volatile("ldmatrix.sync.aligned.m8n8.x4.shared.b16 {%0,%1,%2,%3}, [%4];"
                 : "=r"(r[0]), "=r"(r[1]), "=r"(r[2]), "=r"(r[3]) : "r"(addr));
}
__device__ __forceinline__ void mma_bf16(float* c, const uint32_t* a, const uint32_t* b) {
    asm volatile(
        "mma.sync.aligned.m16n8k16.row.col.f32.bf16.bf16.f32 "
        "{%0,%1,%2,%3}, {%4,%5,%6,%7}, {%8,%9}, {%0,%1,%2,%3};"
        : "+f"(c[0]), "+f"(c[1]), "+f"(c[2]), "+f"(c[3])
        : "r"(a[0]), "r"(a[1]), "r"(a[2]), "r"(a[3]), "r"(b[0]), "r"(b[1]));
}

// ---------------- math ----------------
__device__ __forceinline__ float neg_softplus(float k) {
    float e = __expf(-fabsf(k));
    return -(fmaxf(k, 0.0f) + __logf(1.0f + e));
}
__device__ __forceinline__ float log_g(float p) {
    float e = __expf(-fabsf(p));
    return (p >= 0.0f) ? __logf(p + 0.5f) : (p - __logf(1.0f + e));
}
__device__ __forceinline__ float laddexp(float a, float b) {
    float mx = fmaxf(a, b);
    float e  = __expf(-fabsf(a - b));
    return mx + __logf(1.0f + e);
}

// ============================================================================
// Pre-convert: x (fp32) -> hi/lo bf16
// ============================================================================
__global__ void convert_x_kernel(const float* __restrict__ x)
{
    size_t i = (size_t)blockIdx.x * 256 + threadIdx.x;   // one float4 per thread
    float4 v = reinterpret_cast<const float4*>(x)[i];
    float f[4] = {v.x, v.y, v.z, v.w};
    unsigned long long uh = 0, ul = 0;
    #pragma unroll
    for (int j = 0; j < 4; j++) {
        __nv_bfloat16 hi = __float2bfloat16(f[j]);
        __nv_bfloat16 lo = __float2bfloat16(f[j] - __bfloat162float(hi));
        uh |= (unsigned long long)__bfloat16_as_ushort(hi) << (16 * j);
        ul |= (unsigned long long)__bfloat16_as_ushort(lo) << (16 * j);
    }
    reinterpret_cast<unsigned long long*>(g_xhi)[i] = uh;
    reinterpret_cast<unsigned long long*>(g_xlo)[i] = ul;
}

// Pack weights interleaved: row R -> (R odd ? Wh : Wz)[R>>1], hi/lo split.
__global__ void pack_w_kernel(const float* __restrict__ Wh, const float* __restrict__ Wz)
{
    int R = blockIdx.x;
    int t = threadIdx.x;            // 128 threads, 4 cols each
    const float* src = (R & 1) ? (Wh + (size_t)(R >> 1) * DD) : (Wz + (size_t)(R >> 1) * DD);
    float4 v = *reinterpret_cast<const float4*>(src + t * 4);
    float f[4] = {v.x, v.y, v.z, v.w};
    unsigned long long uh = 0, ul = 0;
    #pragma unroll
    for (int q = 0; q < 4; q++) {
        __nv_bfloat16 hi = __float2bfloat16(f[q]);
        __nv_bfloat16 lo = __float2bfloat16(f[q] - __bfloat162float(hi));
        uh |= (unsigned long long)__bfloat16_as_ushort(hi) << (16 * q);
        ul |= (unsigned long long)__bfloat16_as_ushort(lo) << (16 * q);
    }
    reinterpret_cast<unsigned long long*>(g_bhi)[(size_t)R * 128 + t] = uh;
    reinterpret_cast<unsigned long long*>(g_blo)[(size_t)R * 128 + t] = ul;
}

// ============================================================================
// bf16 mma.sync GEMM with folded 3-split: per K-chunk (k=32) load
// xhi/xlo/bhi/blo once; issue hi*hi + lo*hi + hi*lo from the same buffers.
// CTA tile 128m x 256n(packed); 8 warps (2m x 4n), warp tile 64x64.
// 3-stage cp.async pipeline, smem row stride 80B (conflict-free ldmatrix).
// ============================================================================
#define RSTRIDE 80
#define SM_AHI 0
#define SM_ALO 10240            // 128 rows * 80
#define SM_BHI 20480
#define SM_BLO 40960            // B: 256 rows * 80
#define STAGE_BYTES 61440
#define SMEM_TOTAL (3 * STAGE_BYTES)   // 184320

__device__ __forceinline__ void load_chunk(uint32_t sb, int tid, int m0, int j, int cc)
{
    const int k0 = cc * 32;
    uint32_t base = sb + (cc % 3) * STAGE_BYTES;
    const int r   = tid >> 2;        // 0..63
    const int c16 = tid & 3;
    const uint32_t off0 = (uint32_t)(r * RSTRIDE + c16 * 16);
    // A: 128 rows (2 sub-blocks of 64)
    #pragma unroll
    for (int q = 0; q < 2; q++) {
        int row = r + q * 64;
        uint32_t off = off0 + q * 64 * RSTRIDE;
        size_t gi = (size_t)(m0 + row) * DD + k0 + c16 * 8;
        cpasync16(base + SM_AHI + off, g_xhi + gi);
        cpasync16(base + SM_ALO + off, g_xlo + gi);
    }
    // B: 256 rows (4 sub-blocks of 64)
    #pragma unroll
    for (int q = 0; q < 4; q++) {
        int row = r + q * 64;
        uint32_t off = off0 + q * 64 * RSTRIDE;
        size_t gi = (size_t)(j * 256 + row) * DD + k0 + c16 * 8;
        cpasync16(base + SM_BHI + off, g_bhi + gi);
        cpasync16(base + SM_BLO + off, g_blo + gi);
    }
}

__global__ __launch_bounds__(256, 1) void gemm_mma_kernel(
    const float* __restrict__ pbh, const float* __restrict__ pbz)
{
    extern __shared__ char smem[];
    uint32_t sb = smem_u32(smem);
    const int tid  = threadIdx.x;
    const int lane = tid & 31;
    const int wid  = tid >> 5;
    const int wm   = wid & 1;        // m half: rows [wm*64, wm*64+64)
    const int wn   = wid >> 1;       // n quarter: packed cols [wn*64, +64)
    const int j    = blockIdx.x;     // packed col tile [j*256, +256)
    const int m0   = blockIdx.y * 128;

    float acc[4][8][4];
    #pragma unroll
    for (int tm = 0; tm < 4; tm++)
        #pragma unroll
        for (int nt = 0; nt < 8; nt++)
            #pragma unroll
            for (int e = 0; e < 4; e++) acc[tm][nt][e] = 0.0f;

    // prologue: stages 0..2
    #pragma unroll
    for (int s = 0; s < 3; s++) {
        load_chunk(sb, tid, m0, j, s);
        asm volatile("cp.async.commit_group;" ::: "memory");
    }

    const int arow = (lane & 7) + ((lane >> 3) & 1) * 8;   // A ldmatrix row
    const int akh  = lane >> 4;                            // A k-half
    const int bnr  = ((lane >> 4) << 3) + (lane & 7);      // B ldmatrix n-row
    const int bkh  = (lane >> 3) & 1;                      // B k-half

    for (int cc = 0; cc < 16; cc++) {
        if (cc < 14)       asm volatile("cp.async.wait_group 2;" ::: "memory");
        else if (cc == 14) asm volatile("cp.async.wait_group 1;" ::: "memory");
        else               asm volatile("cp.async.wait_group 0;" ::: "memory");
        __syncthreads();

        const uint32_t st    = sb + (cc % 3) * STAGE_BYTES;
        const uint32_t abase = st + wm * 64 * RSTRIDE;
        const uint32_t bbase = st + wn * 64 * RSTRIDE;

        #pragma unroll
        for (int kk = 0; kk < 2; kk++) {
            uint32_t ah[4][4], al[4][4];
            #pragma unroll
            for (int tm = 0; tm < 4; tm++) {
                uint32_t ro = (uint32_t)((tm * 16 + arow) * RSTRIDE + kk * 32 + akh * 16);
                ldsm_x4(ah[tm], abase + SM_AHI + ro);
                ldsm_x4(al[tm], abase + SM_ALO + ro);
            }
            uint32_t bhf[8][2], blf[8][2];
            #pragma unroll
            for (int g = 0; g < 4; g++) {
                uint32_t ro = (uint32_t)((g * 16 + bnr) * RSTRIDE + kk * 32 + bkh * 16);
                uint32_t r4[4];
                ldsm_x4(r4, bbase + SM_BHI + ro);
                bhf[2 * g][0] = r4[0]; bhf[2 * g][1] = r4[1];
                bhf[2 * g + 1][0] = r4[2]; bhf[2 * g + 1][1] = r4[3];
                ldsm_x4(r4, bbase + SM_BLO + ro);
                blf[2 * g][0] = r4[0]; blf[2 * g][1] = r4[1];
                blf[2 * g + 1][0] = r4[2]; blf[2 * g + 1][1] = r4[3];
            }
            #pragma unroll
            for (int tm = 0; tm < 4; tm++)
                #pragma unroll
                for (int nt = 0; nt < 8; nt++) {
                    mma_bf16(acc[tm][nt], ah[tm], bhf[nt]);
                    mma_bf16(acc[tm][nt], al[tm], bhf[nt]);
                    mma_bf16(acc[tm][nt], ah[tm], blf[nt]);
                }
        }

        __syncthreads();           // all warps done reading buffer cc%3
        if (cc + 3 < 16) {
            load_chunk(sb, tid, m0, j, cc + 3);
            asm volatile("cp.async.commit_group;" ::: "memory");
        }
    }

    // ---- fused epilogue: c-frag col pairs (even,odd) = (k, p) for one h ----
    float bzr[8], bhr[8];
    #pragma unroll
    for (int nt = 0; nt < 8; nt++) {
        int h = j * 128 + wn * 32 + nt * 4 + (lane & 3);
        bzr[nt] = pbz[h];
        bhr[nt] = pbh[h];
    }
    #pragma unroll
    for (int tm = 0; tm < 4; tm++) {
        int r0 = m0 + wm * 64 + tm * 16 + (lane >> 2);
        #pragma unroll
        for (int nt = 0; nt < 8; nt++) {
            int h = j * 128 + wn * 32 + nt * 4 + (lane & 3);
            float k0 = acc[tm][nt][0] + bzr[nt];
            float p0 = acc[tm][nt][1] + bhr[nt];
            float c0 = neg_softplus(k0);
            g_cv[(size_t)r0 * HH + h] = make_float2(c0, k0 + c0 + log_g(p0));
            float k1 = acc[tm][nt][2] + bzr[nt];
            float p1 = acc[tm][nt][3] + bhr[nt];
            float c1 = neg_softplus(k1);
            g_cv[(size_t)(r0 + 8) * HH + h] = make_float2(c1, k1 + c1 + log_g(p1));
        }
    }
}

// ============================================================================
// Scan kernels (HBM-bound, unchanged)
// ============================================================================
__global__ void scan_partial_kernel()
{
    int gt = blockIdx.x * blockDim.x + threadIdx.x;
    int h     = gt & (HH - 1);
    int rest  = gt >> 9;
    int chunk = rest & (NC - 1);
    int b     = rest >> 6;
    const float2* p = g_cv + ((size_t)b * TT + (size_t)chunk * CL) * HH + h;
    float C = 0.0f, V = -INFINITY;
    #pragma unroll 4
    for (int t = 0; t < CL; t++) {
        float2 e = p[(size_t)t * HH];
        C += e.x;
        V = laddexp(V + e.x, e.y);
    }
    g_agg[gt] = make_float2(C, V);
}

__global__ void scan_carry_kernel(const float* __restrict__ hprev)
{
    int gt = blockIdx.x * blockDim.x + threadIdx.x;
    int h = gt & (HH - 1);
    int b = gt >> 9;
    float M = __logf(hprev[(size_t)b * HH + h]);
    #pragma unroll 4
    for (int j = 0; j < NC; j++) {
        size_t idx = ((size_t)b * NC + j) * HH + h;
        g_pref[idx] = M;
        float2 a = g_agg[idx];
        M = laddexp(M + a.x, a.y);
    }
}

__global__ void scan_apply_kernel(float* __restrict__ out)
{
    int gt = blockIdx.x * blockDim.x + threadIdx.x;
    int h     = gt & (HH - 1);
    int rest  = gt >> 9;
    int chunk = rest & (NC - 1);
    int b     = rest >> 6;
    float m = g_pref[gt];
    size_t base = ((size_t)b * TT + (size_t)chunk * CL) * HH + h;
    const float2* p = g_cv + base;
    float* o = out + base;
    #pragma unroll 4
    for (int t = 0; t < CL; t++) {
        float2 e = p[(size_t)t * HH];
        m = laddexp(m + e.x, e.y);
        o[(size_t)t * HH] = __expf(m);
    }
}

// ============================================================================
extern "C" void kernel_launch(void* const* d_in, const int* in_sizes, int n_in,
                              void* d_out, int out_size)
{
    (void)in_sizes; (void)n_in; (void)out_size;
    const float* x  = (const float*)d_in[0];
    const float* hp = (const float*)d_in[1];
    const float* Wh = (const float*)d_in[2];
    const float* bh = (const float*)d_in[3];
    const float* Wz = (const float*)d_in[4];
    const float* bz = (const float*)d_in[5];
    float* out = (float*)d_out;

    cudaFuncSetAttribute(gemm_mma_kernel, cudaFuncAttributeMaxDynamicSharedMemorySize, SMEM_TOTAL);

    convert_x_kernel<<<(MROWS * DD / 4) / 256, 256>>>(x);
    pack_w_kernel<<<1024, 128>>>(Wh, Wz);
    gemm_mma_kernel<<<dim3(4, 256), 256, SMEM_TOTAL>>>(bh, bz);
    scan_partial_kernel<<<(BB * NC * HH) / 256, 256>>>();
    scan_carry_kernel<<<(BB * HH) / 256, 256>>>(hp);
    scan_apply_kernel<<<(BB * NC * HH) / 256, 256>>>(out);
}

// round 13
// speedup vs baseline: 1.3566x; 1.3566x over previous
#include <cuda_runtime.h>
#include <cuda_fp16.h>
#include <math.h>
#include <stdint.h>

// Problem dims (fixed): B=4, T=8192, D=512, H=512
#define BB 4
#define TT 8192
#define DD 512
#define HH 512
#define NC 64
#define CL (TT / NC)
#define MROWS (BB * TT)      // 32768 flattened rows

// ---------------- scratch (allocation-free contract) ----------------
__device__ __align__(16) float2 g_cv[(size_t)BB * TT * HH];        // 128 MB
__device__ float2 g_agg[BB * NC * HH];
__device__ float  g_pref[BB * NC * HH];
__device__ __align__(16) __half g_xh[(size_t)MROWS * DD];          // 32 MB
__device__ __align__(16) __half g_xl[(size_t)MROWS * DD];          // 32 MB
__device__ __align__(16) __half g_w[(size_t)1024 * DD];            // packed: row R -> (R&1? Wh : Wz)[R>>1]

// ---------------- helpers ----------------
__device__ __forceinline__ uint32_t smem_u32(const void* p) {
    uint32_t a;
    asm("{ .reg .u64 t; cvta.to.shared.u64 t, %1; cvt.u32.u64 %0, t; }" : "=r"(a) : "l"(p));
    return a;
}
__device__ __forceinline__ void cpasync16(uint32_t dst, const void* src) {
    asm volatile("cp.async.cg.shared.global [%0], [%1], 16;" :: "r"(dst), "l"(src));
}
__device__ __forceinline__ void ldsm_x4(uint32_t* r, uint32_t addr) {
    asm volatile("ldmatrix.sync.aligned.m8n8.x4.shared.b16 {%0,%1,%2,%3}, [%4];"
                 : "=r"(r[0]), "=r"(r[1]), "=r"(r[2]), "=r"(r[3]) : "r"(addr));
}
__device__ __forceinline__ void mma_f16(float* c, const uint32_t* a, const uint32_t* b) {
    asm volatile(
        "mma.sync.aligned.m16n8k16.row.col.f32.f16.f16.f32 "
        "{%0,%1,%2,%3}, {%4,%5,%6,%7}, {%8,%9}, {%0,%1,%2,%3};"
        : "+f"(c[0]), "+f"(c[1]), "+f"(c[2]), "+f"(c[3])
        : "r"(a[0]), "r"(a[1]), "r"(a[2]), "r"(a[3]), "r"(b[0]), "r"(b[1]));
}

// ---------------- math ----------------
__device__ __forceinline__ float neg_softplus(float k) {
    float e = __expf(-fabsf(k));
    return -(fmaxf(k, 0.0f) + __logf(1.0f + e));
}
__device__ __forceinline__ float log_g(float p) {
    float e = __expf(-fabsf(p));
    return (p >= 0.0f) ? __logf(p + 0.5f) : (p - __logf(1.0f + e));
}
__device__ __forceinline__ float laddexp(float a, float b) {
    float mx = fmaxf(a, b);
    float e  = __expf(-fabsf(a - b));
    return mx + __logf(1.0f + e);
}

// ============================================================================
// Pre-convert: x (fp32) -> exact fp16 hi/lo pair
// ============================================================================
__global__ void convert_x_kernel(const float* __restrict__ x)
{
    size_t i = (size_t)blockIdx.x * 256 + threadIdx.x;   // one float4 per thread
    float4 v = reinterpret_cast<const float4*>(x)[i];
    float f[4] = {v.x, v.y, v.z, v.w};
    unsigned long long uh = 0, ul = 0;
    #pragma unroll
    for (int j = 0; j < 4; j++) {
        __half hi = __float2half(f[j]);
        __half lo = __float2half(f[j] - __half2float(hi));
        uh |= (unsigned long long)__half_as_ushort(hi) << (16 * j);
        ul |= (unsigned long long)__half_as_ushort(lo) << (16 * j);
    }
    reinterpret_cast<unsigned long long*>(g_xh)[i] = uh;
    reinterpret_cast<unsigned long long*>(g_xl)[i] = ul;
}

// Pack weights interleaved, single fp16: row R -> (R odd ? Wh : Wz)[R>>1].
__global__ void pack_w_kernel(const float* __restrict__ Wh, const float* __restrict__ Wz)
{
    int R = blockIdx.x;
    int t = threadIdx.x;            // 128 threads, 4 cols each
    const float* src = (R & 1) ? (Wh + (size_t)(R >> 1) * DD) : (Wz + (size_t)(R >> 1) * DD);
    float4 v = *reinterpret_cast<const float4*>(src + t * 4);
    float f[4] = {v.x, v.y, v.z, v.w};
    unsigned long long uw = 0;
    #pragma unroll
    for (int q = 0; q < 4; q++)
        uw |= (unsigned long long)__half_as_ushort(__float2half(f[q])) << (16 * q);
    reinterpret_cast<unsigned long long*>(g_w)[(size_t)R * 128 + t] = uw;
}

// ============================================================================
// fp16 2-product GEMM: k/p = xh*W + xl*W (W single fp16, x exact fp16 pair).
// CTA tile 128m x 128n(packed); 8 warps (4m x 2n), warp tile 32x64.
// Per K-chunk (k=32): load xh/xl/w once; B fragments shared by both products.
// 3-stage cp.async pipeline (post-consume refill), 2 CTAs/SM.
// Smem row stride 80B => conflict-free ldmatrix without swizzle.
// ============================================================================
#define RSTRIDE 80
#define SM_XH 0
#define SM_XL 10240            // 128 rows * 80
#define SM_W  20480
#define STAGE_BYTES 30720
#define SMEM_TOTAL (3 * STAGE_BYTES)   // 92160

__device__ __forceinline__ void load_chunk(uint32_t sb, int tid, int m0, int j, int cc)
{
    const int k0 = cc * 32;
    uint32_t base = sb + (cc % 3) * STAGE_BYTES;
    #pragma unroll
    for (int q = 0; q < 2; q++) {
        int idx = q * 256 + tid;                 // 0..511
        int r   = idx >> 2;                      // 0..127
        int c16 = idx & 3;
        uint32_t off = (uint32_t)(r * RSTRIDE + c16 * 16);
        size_t ga = (size_t)(m0 + r) * DD + k0 + c16 * 8;
        cpasync16(base + SM_XH + off, g_xh + ga);
        cpasync16(base + SM_XL + off, g_xl + ga);
        cpasync16(base + SM_W  + off, g_w + (size_t)(j * 128 + r) * DD + k0 + c16 * 8);
    }
}

__global__ __launch_bounds__(256, 2) void gemm_mma_kernel(
    const float* __restrict__ pbh, const float* __restrict__ pbz)
{
    extern __shared__ char smem[];
    uint32_t sb = smem_u32(smem);
    const int tid  = threadIdx.x;
    const int lane = tid & 31;
    const int wid  = tid >> 5;
    const int wm   = wid & 3;        // warp row (0..3) -> m offset wm*32
    const int wn   = wid >> 2;       // warp col (0..1) -> packed n offset wn*64
    const int j    = blockIdx.x;     // packed col tile [j*128, +128) = 64 h
    const int m0   = blockIdx.y * 128;

    float acc[2][8][4];
    #pragma unroll
    for (int tm = 0; tm < 2; tm++)
        #pragma unroll
        for (int nt = 0; nt < 8; nt++)
            #pragma unroll
            for (int e = 0; e < 4; e++) acc[tm][nt][e] = 0.0f;

    // prologue: stages 0..2
    #pragma unroll
    for (int s = 0; s < 3; s++) {
        load_chunk(sb, tid, m0, j, s);
        asm volatile("cp.async.commit_group;" ::: "memory");
    }

    const int arow = (lane & 7) + ((lane >> 3) & 1) * 8;   // A ldmatrix row
    const int akh  = lane >> 4;                            // A k-half
    const int bnr  = ((lane >> 4) << 3) + (lane & 7);      // B ldmatrix n-row
    const int bkh  = (lane >> 3) & 1;                      // B k-half

    for (int cc = 0; cc < 16; cc++) {
        if (cc < 14)       asm volatile("cp.async.wait_group 2;" ::: "memory");
        else if (cc == 14) asm volatile("cp.async.wait_group 1;" ::: "memory");
        else               asm volatile("cp.async.wait_group 0;" ::: "memory");
        __syncthreads();

        const uint32_t st    = sb + (cc % 3) * STAGE_BYTES;
        const uint32_t abase = st + wm * 32 * RSTRIDE;
        const uint32_t bbase = st + SM_W + wn * 64 * RSTRIDE;

        #pragma unroll
        for (int kk = 0; kk < 2; kk++) {
            uint32_t ah[2][4], al[2][4];
            #pragma unroll
            for (int tm = 0; tm < 2; tm++) {
                uint32_t ro = (uint32_t)((tm * 16 + arow) * RSTRIDE + kk * 32 + akh * 16);
                ldsm_x4(ah[tm], abase + SM_XH + ro);
                ldsm_x4(al[tm], abase + SM_XL + ro);
            }
            uint32_t b[8][2];
            #pragma unroll
            for (int g = 0; g < 4; g++) {
                uint32_t r4[4];
                ldsm_x4(r4, bbase + (uint32_t)((g * 16 + bnr) * RSTRIDE + kk * 32 + bkh * 16));
                b[2 * g][0] = r4[0]; b[2 * g][1] = r4[1];
                b[2 * g + 1][0] = r4[2]; b[2 * g + 1][1] = r4[3];
            }
            #pragma unroll
            for (int tm = 0; tm < 2; tm++)
                #pragma unroll
                for (int nt = 0; nt < 8; nt++) {
                    mma_f16(acc[tm][nt], ah[tm], b[nt]);
                    mma_f16(acc[tm][nt], al[tm], b[nt]);
                }
        }

        __syncthreads();           // all warps done reading buffer cc%3
        if (cc + 3 < 16) {
            load_chunk(sb, tid, m0, j, cc + 3);
            asm volatile("cp.async.commit_group;" ::: "memory");
        }
    }

    // ---- fused epilogue: c-frag col pairs (even,odd) = (k, p) for one h ----
    float bzr[8], bhr[8];
    #pragma unroll
    for (int nt = 0; nt < 8; nt++) {
        int h = (j * 128 + wn * 64 + nt * 8 + (lane & 3) * 2) >> 1;
        bzr[nt] = pbz[h];
        bhr[nt] = pbh[h];
    }
    #pragma unroll
    for (int tm = 0; tm < 2; tm++) {
        int r0 = m0 + wm * 32 + tm * 16 + (lane >> 2);
        #pragma unroll
        for (int nt = 0; nt < 8; nt++) {
            int h = (j * 128 + wn * 64 + nt * 8 + (lane & 3) * 2) >> 1;
            float k0 = acc[tm][nt][0] + bzr[nt];
            float p0 = acc[tm][nt][1] + bhr[nt];
            float c0 = neg_softplus(k0);
            g_cv[(size_t)r0 * HH + h] = make_float2(c0, k0 + c0 + log_g(p0));
            float k1 = acc[tm][nt][2] + bzr[nt];
            float p1 = acc[tm][nt][3] + bhr[nt];
            float c1 = neg_softplus(k1);
            g_cv[(size_t)(r0 + 8) * HH + h] = make_float2(c1, k1 + c1 + log_g(p1));
        }
    }
}

// ============================================================================
// Scan kernels (HBM-bound, unchanged)
// ============================================================================
__global__ void scan_partial_kernel()
{
    int gt = blockIdx.x * blockDim.x + threadIdx.x;
    int h     = gt & (HH - 1);
    int rest  = gt >> 9;
    int chunk = rest & (NC - 1);
    int b     = rest >> 6;
    const float2* p = g_cv + ((size_t)b * TT + (size_t)chunk * CL) * HH + h;
    float C = 0.0f, V = -INFINITY;
    #pragma unroll 4
    for (int t = 0; t < CL; t++) {
        float2 e = p[(size_t)t * HH];
        C += e.x;
        V = laddexp(V + e.x, e.y);
    }
    g_agg[gt] = make_float2(C, V);
}

__global__ void scan_carry_kernel(const float* __restrict__ hprev)
{
    int gt = blockIdx.x * blockDim.x + threadIdx.x;
    int h = gt & (HH - 1);
    int b = gt >> 9;
    float M = __logf(hprev[(size_t)b * HH + h]);
    #pragma unroll 4
    for (int j = 0; j < NC; j++) {
        size_t idx = ((size_t)b * NC + j) * HH + h;
        g_pref[idx] = M;
        float2 a = g_agg[idx];
        M = laddexp(M + a.x, a.y);
    }
}

__global__ void scan_apply_kernel(float* __restrict__ out)
{
    int gt = blockIdx.x * blockDim.x + threadIdx.x;
    int h     = gt & (HH - 1);
    int rest  = gt >> 9;
    int chunk = rest & (NC - 1);
    int b     = rest >> 6;
    float m = g_pref[gt];
    size_t base = ((size_t)b * TT + (size_t)chunk * CL) * HH + h;
    const float2* p = g_cv + base;
    float* o = out + base;
    #pragma unroll 4
    for (int t = 0; t < CL; t++) {
        float2 e = p[(size_t)t * HH];
        m = laddexp(m + e.x, e.y);
        o[(size_t)t * HH] = __expf(m);
    }
}

// ============================================================================
extern "C" void kernel_launch(void* const* d_in, const int* in_sizes, int n_in,
                              void* d_out, int out_size)
{
    (void)in_sizes; (void)n_in; (void)out_size;
    const float* x  = (const float*)d_in[0];
    const float* hp = (const float*)d_in[1];
    const float* Wh = (const float*)d_in[2];
    const float* bh = (const float*)d_in[3];
    const float* Wz = (const float*)d_in[4];
    const float* bz = (const float*)d_in[5];
    float* out = (float*)d_out;

    cudaFuncSetAttribute(gemm_mma_kernel, cudaFuncAttributeMaxDynamicSharedMemorySize, SMEM_TOTAL);

    convert_x_kernel<<<(MROWS * DD / 4) / 256, 256>>>(x);
    pack_w_kernel<<<1024, 128>>>(Wh, Wz);
    gemm_mma_kernel<<<dim3(8, 256), 256, SMEM_TOTAL>>>(bh, bz);
    scan_partial_kernel<<<(BB * NC * HH) / 256, 256>>>();
    scan_carry_kernel<<<(BB * HH) / 256, 256>>>(hp);
    scan_apply_kernel<<<(BB * NC * HH) / 256, 256>>>(out);
}

// round 14
// speedup vs baseline: 1.8731x; 1.3807x over previous
#include <cuda_runtime.h>
#include <cuda_fp16.h>
#include <math.h>
#include <stdint.h>

// Problem dims (fixed): B=4, T=8192, D=512, H=512
#define BB 4
#define TT 8192
#define DD 512
#define HH 512
#define NC 64
#define CL (TT / NC)
#define MROWS (BB * TT)      // 32768 flattened rows

// ---------------- scratch (allocation-free contract) ----------------
__device__ __align__(16) float2 g_cv[(size_t)BB * TT * HH];        // 128 MB
__device__ __align__(16) float2 g_agg[BB * NC * HH];
__device__ __align__(16) float  g_pref[BB * NC * HH];
__device__ __align__(16) __half g_xh[(size_t)MROWS * DD];          // 32 MB
__device__ __align__(16) __half g_w[(size_t)1024 * DD];            // packed: row R -> (R&1? Wh : Wz)[R>>1]

// ---------------- helpers ----------------
__device__ __forceinline__ uint32_t smem_u32(const void* p) {
    uint32_t a;
    asm("{ .reg .u64 t; cvta.to.shared.u64 t, %1; cvt.u32.u64 %0, t; }" : "=r"(a) : "l"(p));
    return a;
}
__device__ __forceinline__ void cpasync16(uint32_t dst, const void* src) {
    asm volatile("cp.async.cg.shared.global [%0], [%1], 16;" :: "r"(dst), "l"(src));
}
__device__ __forceinline__ void ldsm_x4(uint32_t* r, uint32_t addr) {
    asm volatile("ldmatrix.sync.aligned.m8n8.x4.shared.b16 {%0,%1,%2,%3}, [%4];"
                 : "=r"(r[0]), "=r"(r[1]), "=r"(r[2]), "=r"(r[3]) : "r"(addr));
}
__device__ __forceinline__ void mma_f16(float* c, const uint32_t* a, const uint32_t* b) {
    asm volatile(
        "mma.sync.aligned.m16n8k16.row.col.f32.f16.f16.f32 "
        "{%0,%1,%2,%3}, {%4,%5,%6,%7}, {%8,%9}, {%0,%1,%2,%3};"
        : "+f"(c[0]), "+f"(c[1]), "+f"(c[2]), "+f"(c[3])
        : "r"(a[0]), "r"(a[1]), "r"(a[2]), "r"(a[3]), "r"(b[0]), "r"(b[1]));
}

// ---------------- math ----------------
__device__ __forceinline__ float neg_softplus(float k) {
    float e = __expf(-fabsf(k));
    return -(fmaxf(k, 0.0f) + __logf(1.0f + e));
}
__device__ __forceinline__ float log_g(float p) {
    float e = __expf(-fabsf(p));
    return (p >= 0.0f) ? __logf(p + 0.5f) : (p - __logf(1.0f + e));
}
__device__ __forceinline__ float laddexp(float a, float b) {
    float mx = fmaxf(a, b);
    float e  = __expf(-fabsf(a - b));
    return mx + __logf(1.0f + e);
}

// ============================================================================
// Pre-convert: x (fp32) -> fp16
// ============================================================================
__global__ void convert_x_kernel(const float* __restrict__ x)
{
    size_t i = (size_t)blockIdx.x * 256 + threadIdx.x;   // one float4 per thread
    float4 v = reinterpret_cast<const float4*>(x)[i];
    float f[4] = {v.x, v.y, v.z, v.w};
    unsigned long long uh = 0;
    #pragma unroll
    for (int j = 0; j < 4; j++)
        uh |= (unsigned long long)__half_as_ushort(__float2half(f[j])) << (16 * j);
    reinterpret_cast<unsigned long long*>(g_xh)[i] = uh;
}

// Pack weights interleaved, single fp16: row R -> (R odd ? Wh : Wz)[R>>1].
__global__ void pack_w_kernel(const float* __restrict__ Wh, const float* __restrict__ Wz)
{
    int R = blockIdx.x;
    int t = threadIdx.x;            // 128 threads, 4 cols each
    const float* src = (R & 1) ? (Wh + (size_t)(R >> 1) * DD) : (Wz + (size_t)(R >> 1) * DD);
    float4 v = *reinterpret_cast<const float4*>(src + t * 4);
    float f[4] = {v.x, v.y, v.z, v.w};
    unsigned long long uw = 0;
    #pragma unroll
    for (int q = 0; q < 4; q++)
        uw |= (unsigned long long)__half_as_ushort(__float2half(f[q])) << (16 * q);
    reinterpret_cast<unsigned long long*>(g_w)[(size_t)R * 128 + t] = uw;
}

// ============================================================================
// Single-product fp16 GEMM: k/p = xh * W, fp32 accumulate.
// CTA tile 128m x 128n(packed); 8 warps (4m x 2n), warp tile 32x64.
// 3-stage cp.async pipeline (post-consume refill), 2 CTAs/SM.
// Smem row stride 80B => conflict-free ldmatrix without swizzle.
// ============================================================================
#define RSTRIDE 80
#define SM_XH 0
#define SM_W  10240            // 128 rows * 80
#define STAGE_BYTES 20480
#define SMEM_TOTAL (3 * STAGE_BYTES)   // 61440

__device__ __forceinline__ void load_chunk(uint32_t sb, int tid, int m0, int j, int cc)
{
    const int k0 = cc * 32;
    uint32_t base = sb + (cc % 3) * STAGE_BYTES;
    #pragma unroll
    for (int q = 0; q < 2; q++) {
        int idx = q * 256 + tid;                 // 0..511
        int r   = idx >> 2;                      // 0..127
        int c16 = idx & 3;
        uint32_t off = (uint32_t)(r * RSTRIDE + c16 * 16);
        cpasync16(base + SM_XH + off, g_xh + (size_t)(m0 + r) * DD + k0 + c16 * 8);
        cpasync16(base + SM_W  + off, g_w + (size_t)(j * 128 + r) * DD + k0 + c16 * 8);
    }
}

__global__ __launch_bounds__(256, 2) void gemm_mma_kernel(
    const float* __restrict__ pbh, const float* __restrict__ pbz)
{
    extern __shared__ char smem[];
    uint32_t sb = smem_u32(smem);
    const int tid  = threadIdx.x;
    const int lane = tid & 31;
    const int wid  = tid >> 5;
    const int wm   = wid & 3;        // warp row (0..3) -> m offset wm*32
    const int wn   = wid >> 2;       // warp col (0..1) -> packed n offset wn*64
    const int j    = blockIdx.x;     // packed col tile [j*128, +128) = 64 h
    const int m0   = blockIdx.y * 128;

    float acc[2][8][4];
    #pragma unroll
    for (int tm = 0; tm < 2; tm++)
        #pragma unroll
        for (int nt = 0; nt < 8; nt++)
            #pragma unroll
            for (int e = 0; e < 4; e++) acc[tm][nt][e] = 0.0f;

    // prologue: stages 0..2
    #pragma unroll
    for (int s = 0; s < 3; s++) {
        load_chunk(sb, tid, m0, j, s);
        asm volatile("cp.async.commit_group;" ::: "memory");
    }

    const int arow = (lane & 7) + ((lane >> 3) & 1) * 8;   // A ldmatrix row
    const int akh  = lane >> 4;                            // A k-half
    const int bnr  = ((lane >> 4) << 3) + (lane & 7);      // B ldmatrix n-row
    const int bkh  = (lane >> 3) & 1;                      // B k-half

    for (int cc = 0; cc < 16; cc++) {
        if (cc < 14)       asm volatile("cp.async.wait_group 2;" ::: "memory");
        else if (cc == 14) asm volatile("cp.async.wait_group 1;" ::: "memory");
        else               asm volatile("cp.async.wait_group 0;" ::: "memory");
        __syncthreads();

        const uint32_t st    = sb + (cc % 3) * STAGE_BYTES;
        const uint32_t abase = st + SM_XH + wm * 32 * RSTRIDE;
        const uint32_t bbase = st + SM_W + wn * 64 * RSTRIDE;

        #pragma unroll
        for (int kk = 0; kk < 2; kk++) {
            uint32_t a[2][4];
            #pragma unroll
            for (int tm = 0; tm < 2; tm++)
                ldsm_x4(a[tm], abase + (uint32_t)((tm * 16 + arow) * RSTRIDE + kk * 32 + akh * 16));
            uint32_t b[8][2];
            #pragma unroll
            for (int g = 0; g < 4; g++) {
                uint32_t r4[4];
                ldsm_x4(r4, bbase + (uint32_t)((g * 16 + bnr) * RSTRIDE + kk * 32 + bkh * 16));
                b[2 * g][0] = r4[0]; b[2 * g][1] = r4[1];
                b[2 * g + 1][0] = r4[2]; b[2 * g + 1][1] = r4[3];
            }
            #pragma unroll
            for (int tm = 0; tm < 2; tm++)
                #pragma unroll
                for (int nt = 0; nt < 8; nt++)
                    mma_f16(acc[tm][nt], a[tm], b[nt]);
        }

        __syncthreads();           // all warps done reading buffer cc%3
        if (cc + 3 < 16) {
            load_chunk(sb, tid, m0, j, cc + 3);
            asm volatile("cp.async.commit_group;" ::: "memory");
        }
    }

    // ---- fused epilogue: c-frag col pairs (even,odd) = (k, p) for one h ----
    float bzr[8], bhr[8];
    #pragma unroll
    for (int nt = 0; nt < 8; nt++) {
        int h = (j * 128 + wn * 64 + nt * 8 + (lane & 3) * 2) >> 1;
        bzr[nt] = pbz[h];
        bhr[nt] = pbh[h];
    }
    #pragma unroll
    for (int tm = 0; tm < 2; tm++) {
        int r0 = m0 + wm * 32 + tm * 16 + (lane >> 2);
        #pragma unroll
        for (int nt = 0; nt < 8; nt++) {
            int h = (j * 128 + wn * 64 + nt * 8 + (lane & 3) * 2) >> 1;
            float k0 = acc[tm][nt][0] + bzr[nt];
            float p0 = acc[tm][nt][1] + bhr[nt];
            float c0 = neg_softplus(k0);
            g_cv[(size_t)r0 * HH + h] = make_float2(c0, k0 + c0 + log_g(p0));
            float k1 = acc[tm][nt][2] + bzr[nt];
            float p1 = acc[tm][nt][3] + bhr[nt];
            float c1 = neg_softplus(k1);
            g_cv[(size_t)(r0 + 8) * HH + h] = make_float2(c1, k1 + c1 + log_g(p1));
        }
    }
}

// ============================================================================
// Kernel 2: per-chunk partials; each thread handles TWO adjacent h (float4).
// ============================================================================
__global__ void scan_partial_kernel()
{
    int u = blockIdx.x * blockDim.x + threadIdx.x;   // BB*NC*HH/2 threads
    int h2    = u & 255;            // h pair index -> h = 2*h2
    int rest  = u >> 8;
    int chunk = rest & (NC - 1);
    int b     = rest >> 6;
    const float4* p = reinterpret_cast<const float4*>(
        g_cv + ((size_t)b * TT + (size_t)chunk * CL) * HH + 2 * h2);
    float C0 = 0.0f, V0 = -INFINITY, C1 = 0.0f, V1 = -INFINITY;
    #pragma unroll 4
    for (int t = 0; t < CL; t++) {
        float4 e = p[(size_t)t * (HH / 2)];
        C0 += e.x;  V0 = laddexp(V0 + e.x, e.y);
        C1 += e.z;  V1 = laddexp(V1 + e.z, e.w);
    }
    float4* agg = reinterpret_cast<float4*>(g_agg);
    agg[u] = make_float4(C0, V0, C1, V1);     // = g_agg[2u], g_agg[2u+1]
}

// ============================================================================
// Kernel 3: scan chunk aggregates per (b,h), seeded with log(h_prev).
// ============================================================================
__global__ void scan_carry_kernel(const float* __restrict__ hprev)
{
    int gt = blockIdx.x * blockDim.x + threadIdx.x;  // BB*HH threads
    int h = gt & (HH - 1);
    int b = gt >> 9;
    float M = __logf(hprev[(size_t)b * HH + h]);
    #pragma unroll 4
    for (int j = 0; j < NC; j++) {
        size_t idx = ((size_t)b * NC + j) * HH + h;
        g_pref[idx] = M;
        float2 a = g_agg[idx];
        M = laddexp(M + a.x, a.y);
    }
}

// ============================================================================
// Kernel 4: apply — two adjacent h per thread (float4 read, float2 write).
// ============================================================================
__global__ void scan_apply_kernel(float* __restrict__ out)
{
    int u = blockIdx.x * blockDim.x + threadIdx.x;
    int h2    = u & 255;
    int rest  = u >> 8;
    int chunk = rest & (NC - 1);
    int b     = rest >> 6;
    float2 m2 = *reinterpret_cast<const float2*>(g_pref + (size_t)rest * HH + 2 * h2);
    float m0 = m2.x, m1 = m2.y;
    size_t base = ((size_t)b * TT + (size_t)chunk * CL) * HH + 2 * h2;
    const float4* p = reinterpret_cast<const float4*>(g_cv + base);
    float2* o = reinterpret_cast<float2*>(out + base);
    #pragma unroll 4
    for (int t = 0; t < CL; t++) {
        float4 e = p[(size_t)t * (HH / 2)];
        m0 = laddexp(m0 + e.x, e.y);
        m1 = laddexp(m1 + e.z, e.w);
        o[(size_t)t * (HH / 2)] = make_float2(__expf(m0), __expf(m1));
    }
}

// ============================================================================
extern "C" void kernel_launch(void* const* d_in, const int* in_sizes, int n_in,
                              void* d_out, int out_size)
{
    (void)in_sizes; (void)n_in; (void)out_size;
    const float* x  = (const float*)d_in[0];
    const float* hp = (const float*)d_in[1];
    const float* Wh = (const float*)d_in[2];
    const float* bh = (const float*)d_in[3];
    const float* Wz = (const float*)d_in[4];
    const float* bz = (const float*)d_in[5];
    float* out = (float*)d_out;

    cudaFuncSetAttribute(gemm_mma_kernel, cudaFuncAttributeMaxDynamicSharedMemorySize, SMEM_TOTAL);

    convert_x_kernel<<<(MROWS * DD / 4) / 256, 256>>>(x);
    pack_w_kernel<<<1024, 128>>>(Wh, Wz);
    gemm_mma_kernel<<<dim3(8, 256), 256, SMEM_TOTAL>>>(bh, bz);
    scan_partial_kernel<<<(BB * NC * HH / 2) / 256, 256>>>();
    scan_carry_kernel<<<(BB * HH) / 256, 256>>>(hp);
    scan_apply_kernel<<<(BB * NC * HH / 2) / 256, 256>>>(out);
}